// round 12
// baseline (speedup 1.0000x reference)
#include <cuda_runtime.h>

#define NBOX 16384
#define NW   256            // 64-bit words per mask row
#define NBKT 16384          // conf buckets for counting sort
#define NBLK 128            // persistent CTAs (<= SM count)
#define THR  256
#define CONF_THRESH 0.5f
#define PIOU_THRESH 0.5f

typedef unsigned long long u64;

// ---------------- device scratch (static; no allocation) ----------------
__device__ float4 g_seph[NBOX];                    // sorted [start,end,peak,height]
__device__ float  g_conf[NBOX];                    // dense confidence (unsorted)
__device__ int    g_hist[NBKT];
__device__ int    g_off[NBKT];
__device__ int    g_cnt[NBKT];
__device__ int    g_blist[NBOX];
__device__ int    g_M;
__device__ u64    g_mask[(size_t)NBOX * NW];       // 32MB suppression bitmask
__device__ u64    g_D[NW];                         // definitely-kept bitmap
__device__ u64    g_suppD[NW];                     // accumulated suppr(D)
__device__ int    g_ulist[2][NBOX];
__device__ int    g_dlist[2][NBOX];
__device__ int    g_un[2], g_dn[2];
__device__ int    g_part[NBLK];                    // per-segment sums
__device__ int    g_partoff[NBLK];                 // suffix-exclusive of g_part
__device__ int    g_bar_count;
__device__ int    g_bar_gen;
__device__ int    g_diff;

__device__ __forceinline__ int bucket_of(float c) {
    int b = (int)(c * 16384.0f);                   // exact pow2 mul; monotone
    return b > 16383 ? 16383 : b;
}

// grid barrier: atomic arrival, VOLATILE-LOAD spin (no RMW poll serialization)
__device__ __forceinline__ void gridsync(int& gen) {
    __syncthreads();
    if (threadIdx.x == 0) {
        __threadfence();                           // publish our writes
        if (atomicAdd(&g_bar_count, 1) == NBLK - 1) {
            g_bar_count = 0;
            __threadfence();
            *(volatile int*)&g_bar_gen = gen + 1;  // release
        } else {
            while (*(volatile int*)&g_bar_gen - gen <= 0) { }
        }
        gen++;
        __threadfence();                           // acquire
    }
    __syncthreads();
}

__device__ __forceinline__ u64 trim_diag(u64 v, int j, int wtop) {
    if (j >= wtop) {                               // diagonal word: keep bits > bj
        int bj = j & 63;
        v = (bj == 63) ? 0ULL : (v & (~0ULL << (bj + 1)));
    }
    return v;
}

__device__ __forceinline__ u64 block_or(u64 v, u64* s_acc) {
#pragma unroll
    for (int o = 16; o > 0; o >>= 1)
        v |= __shfl_down_sync(0xffffffffu, v, o);
    if ((threadIdx.x & 31) == 0) s_acc[threadIdx.x >> 5] = v;
    __syncthreads();
    u64 r = 0ULL;
    if (threadIdx.x == 0) {
#pragma unroll
        for (int k = 0; k < 8; k++) r |= s_acc[k];
    }
    return r;                                      // valid on thread 0 only
}

__global__ void __launch_bounds__(THR, 1) k_all(const float* __restrict__ in,
                                                float4* __restrict__ out) {
    __shared__ float4 s_cols[4][64];
    __shared__ int    s_scan[128];
    __shared__ u64    s_acc[8];
    __shared__ int    s_cont;
    int tid  = threadIdx.x;
    int bid  = blockIdx.x;
    int gtid = bid * THR + tid;                    // 0..32767
    int gen = 0;
    if (tid == 0) gen = *(volatile int*)&g_bar_gen; // replay-safe baseline

    // ---- P0: init everything ----
    if (gtid < NBKT) { g_hist[gtid] = 0; g_cnt[gtid] = 0; }
    if (gtid < NBOX) g_conf[gtid] = in[gtid * 5];
    if (gtid < NW)   { g_suppD[gtid] = 0ULL; g_D[gtid] = 0ULL; }
    if (gtid == 0) {
        g_M = 0; g_diff = 0;
        g_un[0] = g_un[1] = 0; g_dn[0] = g_dn[1] = 0;
    }
    gridsync(gen);                                 // B1

    // ---- P1: bucket histogram ----
    if (gtid < NBOX) atomicAdd(&g_hist[bucket_of(g_conf[gtid])], 1);
    gridsync(gen);                                 // B2

    // ---- P2: per-CTA segment sums (128 buckets per CTA) ----
    {
        int v = (tid < 128) ? g_hist[bid * 128 + tid] : 0;
        if (tid < 128) s_scan[tid] = v;
        __syncthreads();
        if (tid < 64) s_scan[tid] += s_scan[tid + 64]; __syncthreads();
        if (tid < 32) s_scan[tid] += s_scan[tid + 32]; __syncthreads();
        if (tid < 32) {                             // warp-level finish
            int x = s_scan[tid];
#pragma unroll
            for (int o = 16; o > 0; o >>= 1) x += __shfl_down_sync(0xffffffffu, x, o);
            if (tid == 0) g_part[bid] = x;
        }
    }
    gridsync(gen);                                 // B3

    // ---- P3: CTA0 suffix-scans the 128 segment sums ----
    if (bid == 0) {
        int pv = (tid < 128) ? g_part[tid] : 0;
        if (tid < 128) s_scan[tid] = pv;
        __syncthreads();
        for (int o = 1; o < 128; o <<= 1) {
            int x = (tid < 128 && tid + o < 128) ? s_scan[tid + o] : 0;
            __syncthreads();
            if (tid < 128) s_scan[tid] += x;
            __syncthreads();
        }
        if (tid < 128) g_partoff[tid] = s_scan[tid] - pv;   // suffix-exclusive
    }
    gridsync(gen);                                 // B4

    // ---- P4: per-bucket global suffix offsets ----
    {
        int hv = (tid < 128) ? g_hist[bid * 128 + tid] : 0;
        if (tid < 128) s_scan[tid] = hv;
        __syncthreads();
        for (int o = 1; o < 128; o <<= 1) {
            int x = (tid < 128 && tid + o < 128) ? s_scan[tid + o] : 0;
            __syncthreads();
            if (tid < 128) s_scan[tid] += x;
            __syncthreads();
        }
        if (tid < 128)
            g_off[bid * 128 + tid] = g_partoff[bid] + s_scan[tid] - hv;
    }
    gridsync(gen);                                 // B5

    // ---- P5: scatter indices into bucket segments ----
    if (gtid < NBOX) {
        int b = bucket_of(g_conf[gtid]);
        int pos = g_off[b] + atomicAdd(&g_cnt[b], 1);
        g_blist[pos] = gtid;
    }
    gridsync(gen);                                 // B6

    // ---- P6: exact rank within bucket + scatter boxes + count M ----
    if (gtid < NBOX) {
        float ci = g_conf[gtid];
        int b    = bucket_of(ci);
        int base = g_off[b], len = g_hist[b];
        int cnt = 0;
        for (int p = base; p < base + len; p++) {
            int j = g_blist[p];
            float cj = g_conf[j];
            cnt += (cj > ci) || (cj == ci && j < gtid);
        }
        int r = base + cnt;
        const float* row = in + (size_t)gtid * 5;
        g_seph[r] = make_float4(row[1], row[2], row[3], row[4]);
        if (ci > CONF_THRESH) atomicAdd(&g_M, 1);
    }
    gridsync(gen);                                 // B7

    int M  = *(volatile int*)&g_M;
    int Mw = (M + 63) >> 6;

    // ---- P7: pairwise peak-IoU bitmask, triangular tiles ----
    {
        int ntiles = Mw * (Mw + 1) / 2;            // tiles with by <= bx
        int group  = (bid << 2) | (tid >> 6);      // 0..511
        int gl     = tid & 63;
        int lgrp   = tid >> 6;
        int rounds = (ntiles + 511) >> 9;
        for (int rr = 0; rr < rounds; rr++) {
            int t = rr * 512 + group;
            bool active = t < ntiles;
            int by = 0, bx = 0;
            if (active) {
                int rem = t;
                int cnt = Mw;
                while (rem >= cnt) { rem -= cnt; by++; cnt--; }
                bx = by + rem;
            }
            if (active) s_cols[lgrp][gl] = g_seph[(bx << 6) + gl];
            __syncthreads();
            if (active) {
                int r = (by << 6) + gl;
                if (r < M) {
                    float4 a = g_seph[r];
                    float area1 = __fmul_rn(__fsub_rn(a.y, a.x), a.w);
                    u64 w = 0;
#pragma unroll 4
                    for (int k = 0; k < 64; k++) {
                        float4 b = s_cols[lgrp][k];
                        float is = fmaxf(a.x, b.x);
                        float ie = fminf(a.y, b.y);
                        float il = __fsub_rn(ie, is);
                        bool sup = false;
                        if (il > 0.0f) {
                            float inter_h    = fminf(a.w, b.w);
                            float inter_area = __fmul_rn(il, inter_h);
                            float area2      = __fmul_rn(__fsub_rn(b.y, b.x), b.w);
                            float union_area = __fsub_rn(__fadd_rn(area1, area2), inter_area);
                            float iou        = __fdiv_rn(inter_area, union_area);
                            float pd         = fabsf(__fsub_rn(a.z, b.z));
                            float us         = fminf(a.x, b.x);
                            float ue         = fmaxf(a.y, b.y);
                            float ud         = fabsf(__fsub_rn(ue, us));
                            float val        = __fsub_rn(iou, __fdiv_rn(pd, ud));
                            sup = (val > PIOU_THRESH);
                        }
                        w |= ((u64)sup) << k;
                    }
                    int j0  = bx << 6;
                    int lim = M - j0;
                    if (lim < 64) w &= (1ULL << lim) - 1ULL;
                    if (r >= j0 && r < j0 + 64) w &= ~(1ULL << (r - j0));
                    g_mask[(size_t)r * NW + bx] = w;
                }
            }
            __syncthreads();
        }
    }
    gridsync(gen);                                 // B8

    // ---- P8: incremental fixpoint NMS ----
    for (int it = 0;; it++) {
        int e = it & 1;
        if (gtid == 0) g_un[e] = 0;                // next-epoch U counter
        // Phase A: Dnew = valid & ~(suppD | suppr(U_{it-1}))
        for (int w = bid; w < Mw; w += NBLK) {
            int hi   = (w + 1) << 6; if (hi > M) hi = M;
            int wtop = w << 6;
            u64 sup = 0ULL;
            if (it == 0) {                         // U_{-1} = all valid
#pragma unroll 4
                for (int j = tid; j < hi; j += THR)
                    sup |= trim_diag(g_mask[(size_t)j * NW + w], j, wtop);
            } else {
                int n = g_un[1 - e];
                const int* ul = g_ulist[1 - e];
#pragma unroll 4
                for (int p = tid; p < n; p += THR) {
                    int j = ul[p];
                    if (j < hi)
                        sup |= trim_diag(g_mask[(size_t)j * NW + w], j, wtop);
                }
            }
            sup = block_or(sup, s_acc);
            if (tid == 0) {
                sup |= g_suppD[w];
                int lim = M - wtop;
                u64 vm = (lim >= 64) ? ~0ULL : ((1ULL << lim) - 1ULL);
                u64 dn  = vm & ~sup;
                u64 add = dn & ~g_D[w];
                g_D[w] = dn;
                int na = __popcll(add);
                if (na) {
                    int base = atomicAdd(&g_dn[e], na);
                    while (add) {
                        int b = __ffsll((long long)add) - 1;
                        add &= add - 1ULL;
                        g_dlist[e][base++] = wtop + b;
                    }
                }
            }
            __syncthreads();
        }
        gridsync(gen);                             // S1: D + dlist complete
        if (gtid == 0) g_dn[1 - e] = 0;
        // Phase B: suppD |= suppr(Delta); P = valid & ~suppD; build U
        {
            int n = g_dn[e];
            const int* dl = g_dlist[e];
            for (int w = bid; w < Mw; w += NBLK) {
                int hi   = (w + 1) << 6; if (hi > M) hi = M;
                int wtop = w << 6;
                u64 sup = 0ULL;
#pragma unroll 4
                for (int p = tid; p < n; p += THR) {
                    int j = dl[p];
                    if (j < hi)
                        sup |= trim_diag(g_mask[(size_t)j * NW + w], j, wtop);
                }
                sup = block_or(sup, s_acc);
                if (tid == 0) {
                    u64 sd = g_suppD[w] | sup;
                    g_suppD[w] = sd;
                    int lim = M - wtop;
                    u64 vm = (lim >= 64) ? ~0ULL : ((1ULL << lim) - 1ULL);
                    u64 pn   = vm & ~sd;
                    u64 dcur = g_D[w];
                    if (pn != dcur) atomicMax(&g_diff, it + 1);
                    u64 undec = pn & ~dcur;
                    int nu = __popcll(undec);
                    if (nu) {
                        int base = atomicAdd(&g_un[e], nu);
                        while (undec) {
                            int b = __ffsll((long long)undec) - 1;
                            undec &= undec - 1ULL;
                            g_ulist[e][base++] = wtop + b;
                        }
                    }
                }
                __syncthreads();
            }
        }
        gridsync(gen);                             // S2: suppD/diff/ulist complete
        if (tid == 0) s_cont = (*(volatile int*)&g_diff > it);
        __syncthreads();
        if (!s_cont) break;
    }

    // ---- output: keep == D ----
    if (gtid < NBOX) {
        u64 kw = g_D[gtid >> 6];
        float4 v = ((kw >> (gtid & 63)) & 1ULL) ? g_seph[gtid]
                                                : make_float4(0.f, 0.f, 0.f, 0.f);
        out[gtid] = v;
    }
}

extern "C" void kernel_launch(void* const* d_in, const int* in_sizes, int n_in,
                              void* d_out, int out_size) {
    const float* in = (const float*)d_in[0];
    float4* out = (float4*)d_out;
    (void)in_sizes; (void)n_in; (void)out_size;
    k_all<<<NBLK, THR>>>(in, out);
}

// round 15
// speedup vs baseline: 1.2119x; 1.2119x over previous
#include <cuda_runtime.h>

#define NBOX 16384
#define NW   256            // 64-bit words per mask row
#define NBKT 16384          // conf buckets for counting sort
#define NBLK_S 64           // persistent sort CTAs
#define NBLK_F 128          // persistent fixpoint CTAs
#define CONF_THRESH 0.5f
#define PIOU_THRESH 0.5f

typedef unsigned long long u64;

// ---------------- device scratch (static; no allocation) ----------------
__device__ float4 g_seph[NBOX];                    // sorted [start,end,peak,height]
__device__ float  g_conf[NBOX];                    // dense confidence (unsorted)
__device__ int    g_hist[NBKT];
__device__ int    g_off[NBKT];
__device__ int    g_cnt[NBKT];
__device__ int    g_blist[NBOX];
__device__ int    g_M;
__device__ u64    g_mask[(size_t)NBOX * NW];       // 32MB suppression bitmask
__device__ u64    g_D[NW];                         // definitely-kept bitmap
__device__ u64    g_suppD[NW];                     // accumulated suppr(D)
__device__ int    g_ulist[2][NBOX];
__device__ int    g_dlist[2][NBOX];
__device__ int    g_un[2], g_dn[2];
__device__ int    g_part[NBLK_S];                  // per-segment sums
__device__ int    g_partoff[NBLK_S];               // suffix-exclusive of g_part
__device__ int    g_bc_s, g_bg_s;                  // sort barrier
__device__ int    g_bc_f, g_bg_f;                  // fix barrier
__device__ int    g_diff;

__device__ __forceinline__ int bucket_of(float c) {
    int b = (int)(c * 16384.0f);                   // exact pow2 mul; monotone
    return b > 16383 ? 16383 : b;
}

// grid barrier: atomic arrival, volatile-load spin (no RMW poll serialization)
__device__ __forceinline__ void gridsync(int& gen, int nblk, int* cnt, int* flg) {
    __syncthreads();
    if (threadIdx.x == 0) {
        __threadfence();                           // publish our writes
        if (atomicAdd(cnt, 1) == nblk - 1) {
            *cnt = 0;
            __threadfence();
            *(volatile int*)flg = gen + 1;         // release
        } else {
            while (*(volatile int*)flg - gen <= 0) { }
        }
        gen++;
        __threadfence();                           // acquire
    }
    __syncthreads();
}

// ================= 1) fused sort pipeline (64 CTAs x 256) ====================
__global__ void __launch_bounds__(256, 1) k_sort(const float* __restrict__ in) {
    __shared__ int s_scan[256];
    int tid  = threadIdx.x;
    int bid  = blockIdx.x;
    int gtid = bid * 256 + tid;                    // 0..16383
    int gen = 0;
    if (tid == 0) gen = *(volatile int*)&g_bg_s;   // replay-safe baseline

    // P0: init
    g_hist[gtid] = 0;
    g_cnt[gtid]  = 0;
    float ci = in[gtid * 5];
    g_conf[gtid] = ci;
    if (gtid == 0) g_M = 0;
    gridsync(gen, NBLK_S, &g_bc_s, &g_bg_s);       // B1

    // P1: histogram
    int myb = bucket_of(ci);
    atomicAdd(&g_hist[myb], 1);
    gridsync(gen, NBLK_S, &g_bc_s, &g_bg_s);       // B2

    // P2: per-CTA segment sum over its 256 buckets
    int hv = g_hist[gtid];
    s_scan[tid] = hv;
    __syncthreads();
    if (tid < 128) s_scan[tid] += s_scan[tid + 128];
    __syncthreads();
    if (tid < 64)  s_scan[tid] += s_scan[tid + 64];
    __syncthreads();
    if (tid < 32) {
        int x = s_scan[tid] + s_scan[tid + 32];
#pragma unroll
        for (int o = 16; o > 0; o >>= 1) x += __shfl_down_sync(0xffffffffu, x, o);
        if (tid == 0) g_part[bid] = x;
    }
    gridsync(gen, NBLK_S, &g_bc_s, &g_bg_s);       // B3

    // P3: CTA0 suffix-scans the 64 segment sums (ALL 256 threads participate in
    // every __syncthreads; entries >= 64 padded with 0, identity for suffix sum)
    if (bid == 0) {
        int pv = (tid < 64) ? g_part[tid] : 0;
        s_scan[tid] = pv;
        __syncthreads();
        for (int o = 1; o < 64; o <<= 1) {
            int x = (tid + o < 256) ? s_scan[tid + o] : 0;
            __syncthreads();
            s_scan[tid] += x;
            __syncthreads();
        }
        if (tid < 64) g_partoff[tid] = s_scan[tid] - pv;   // suffix-exclusive
    }
    gridsync(gen, NBLK_S, &g_bc_s, &g_bg_s);       // B4

    // P4: per-bucket global suffix offsets (suffix scan of this CTA's 256)
    s_scan[tid] = hv;
    __syncthreads();
    for (int o = 1; o < 256; o <<= 1) {
        int x = (tid + o < 256) ? s_scan[tid + o] : 0;
        __syncthreads();
        s_scan[tid] += x;
        __syncthreads();
    }
    g_off[gtid] = g_partoff[bid] + s_scan[tid] - hv;
    gridsync(gen, NBLK_S, &g_bc_s, &g_bg_s);       // B5

    // P5: scatter indices into bucket segments
    int pos = g_off[myb] + atomicAdd(&g_cnt[myb], 1);
    g_blist[pos] = gtid;
    gridsync(gen, NBLK_S, &g_bc_s, &g_bg_s);       // B6

    // P6: exact rank within bucket + scatter boxes + count M
    {
        int base = g_off[myb], len = g_hist[myb];
        int cnt = 0;
        for (int p = base; p < base + len; p++) {
            int j = g_blist[p];
            float cj = g_conf[j];
            cnt += (cj > ci) || (cj == ci && j < gtid);
        }
        int r = base + cnt;
        const float* row = in + (size_t)gtid * 5;
        g_seph[r] = make_float4(row[1], row[2], row[3], row[4]);
        if (ci > CONF_THRESH) atomicAdd(&g_M, 1);
    }
}

// ================= 2) pairwise peak-IoU bitmask (wide launch) ================
__global__ void k_mask() {
    __shared__ float4 cols[64];
    if (blockIdx.x < blockIdx.y) return;           // triangular: halves the work
    int M = g_M;
    if ((int)(blockIdx.y * 64) >= M) return;
    int j0 = blockIdx.x * 64;
    if (j0 >= M) return;
    int r = blockIdx.y * 64 + threadIdx.x;
    cols[threadIdx.x] = g_seph[j0 + threadIdx.x];
    __syncthreads();
    if (r >= M) return;
    float4 a = g_seph[r];
    float area1 = __fmul_rn(__fsub_rn(a.y, a.x), a.w);
    u64 w = 0;
#pragma unroll 4
    for (int k = 0; k < 64; k++) {
        float4 b = cols[k];
        float is = fmaxf(a.x, b.x);
        float ie = fminf(a.y, b.y);
        float il = __fsub_rn(ie, is);
        bool sup = false;
        if (il > 0.0f) {                           // piou>0 requires overlap
            float inter_h    = fminf(a.w, b.w);
            float inter_area = __fmul_rn(il, inter_h);
            float area2      = __fmul_rn(__fsub_rn(b.y, b.x), b.w);
            float union_area = __fsub_rn(__fadd_rn(area1, area2), inter_area);
            float iou        = __fdiv_rn(inter_area, union_area);
            float pd         = fabsf(__fsub_rn(a.z, b.z));
            float us         = fminf(a.x, b.x);
            float ue         = fmaxf(a.y, b.y);
            float ud         = fabsf(__fsub_rn(ue, us));
            float val        = __fsub_rn(iou, __fdiv_rn(pd, ud));
            sup = (val > PIOU_THRESH);
        }
        w |= ((u64)sup) << k;
    }
    int lim = M - j0;
    if (lim < 64) w &= (1ULL << lim) - 1ULL;
    if (r >= j0 && r < j0 + 64) w &= ~(1ULL << (r - j0));
    g_mask[(size_t)r * NW + blockIdx.x] = w;
}

// ================= 3) persistent incremental fixpoint NMS ====================
__device__ __forceinline__ u64 trim_diag(u64 v, int j, int wtop) {
    if (j >= wtop) {                               // diagonal word: keep bits > bj
        int bj = j & 63;
        v = (bj == 63) ? 0ULL : (v & (~0ULL << (bj + 1)));
    }
    return v;
}

__device__ __forceinline__ u64 block_or(u64 v, u64* s_acc) {
#pragma unroll
    for (int o = 16; o > 0; o >>= 1)
        v |= __shfl_down_sync(0xffffffffu, v, o);
    if ((threadIdx.x & 31) == 0) s_acc[threadIdx.x >> 5] = v;
    __syncthreads();
    u64 r = 0ULL;
    if (threadIdx.x == 0) {
#pragma unroll
        for (int k = 0; k < 8; k++) r |= s_acc[k];
    }
    return r;                                      // valid on thread 0 only
}

__global__ void __launch_bounds__(256, 1) k_fix(float4* __restrict__ out) {
    __shared__ u64 s_acc[8];
    __shared__ int s_cont;
    int tid  = threadIdx.x;
    int bid  = blockIdx.x;
    int gtid = bid * 256 + tid;                    // 0..32767
    int gen = 0;
    if (tid == 0) gen = *(volatile int*)&g_bg_f;   // replay-safe baseline
    int M  = g_M;
    int Mw = (M + 63) >> 6;

    // init
    if (gtid < NW) { g_suppD[gtid] = 0ULL; g_D[gtid] = 0ULL; }
    if (gtid == 0) {
        g_diff = 0;
        g_un[0] = g_un[1] = 0;
        g_dn[0] = g_dn[1] = 0;
    }
    gridsync(gen, NBLK_F, &g_bc_f, &g_bg_f);

    for (int it = 0;; it++) {
        int e = it & 1;
        if (gtid == 0) g_un[e] = 0;                // next-epoch U counter
        // Phase A: Dnew = valid & ~(suppD | suppr(U_{it-1}))
        for (int w = bid; w < Mw; w += NBLK_F) {
            int hi   = (w + 1) << 6; if (hi > M) hi = M;
            int wtop = w << 6;
            u64 sup = 0ULL;
            if (it == 0) {                         // U_{-1} = all valid
#pragma unroll 4
                for (int j = tid; j < hi; j += 256)
                    sup |= trim_diag(g_mask[(size_t)j * NW + w], j, wtop);
            } else {
                int n = g_un[1 - e];
                const int* ul = g_ulist[1 - e];
#pragma unroll 4
                for (int p = tid; p < n; p += 256) {
                    int j = ul[p];
                    if (j < hi)
                        sup |= trim_diag(g_mask[(size_t)j * NW + w], j, wtop);
                }
            }
            sup = block_or(sup, s_acc);
            if (tid == 0) {
                sup |= g_suppD[w];
                int lim = M - wtop;
                u64 vm = (lim >= 64) ? ~0ULL : ((1ULL << lim) - 1ULL);
                u64 dn  = vm & ~sup;
                u64 add = dn & ~g_D[w];
                g_D[w] = dn;
                int na = __popcll(add);
                if (na) {
                    int base = atomicAdd(&g_dn[e], na);
                    while (add) {
                        int b = __ffsll((long long)add) - 1;
                        add &= add - 1ULL;
                        g_dlist[e][base++] = wtop + b;
                    }
                }
            }
            __syncthreads();
        }
        gridsync(gen, NBLK_F, &g_bc_f, &g_bg_f);   // S1: D + dlist complete
        if (gtid == 0) g_dn[1 - e] = 0;
        // Phase B: suppD |= suppr(Delta); P = valid & ~suppD; build U
        {
            int n = g_dn[e];
            const int* dl = g_dlist[e];
            for (int w = bid; w < Mw; w += NBLK_F) {
                int hi   = (w + 1) << 6; if (hi > M) hi = M;
                int wtop = w << 6;
                u64 sup = 0ULL;
#pragma unroll 4
                for (int p = tid; p < n; p += 256) {
                    int j = dl[p];
                    if (j < hi)
                        sup |= trim_diag(g_mask[(size_t)j * NW + w], j, wtop);
                }
                sup = block_or(sup, s_acc);
                if (tid == 0) {
                    u64 sd = g_suppD[w] | sup;
                    g_suppD[w] = sd;
                    int lim = M - wtop;
                    u64 vm = (lim >= 64) ? ~0ULL : ((1ULL << lim) - 1ULL);
                    u64 pn   = vm & ~sd;
                    u64 dcur = g_D[w];
                    if (pn != dcur) atomicMax(&g_diff, it + 1);
                    u64 undec = pn & ~dcur;
                    int nu = __popcll(undec);
                    if (nu) {
                        int base = atomicAdd(&g_un[e], nu);
                        while (undec) {
                            int b = __ffsll((long long)undec) - 1;
                            undec &= undec - 1ULL;
                            g_ulist[e][base++] = wtop + b;
                        }
                    }
                }
                __syncthreads();
            }
        }
        gridsync(gen, NBLK_F, &g_bc_f, &g_bg_f);   // S2: suppD/diff/ulist complete
        if (tid == 0) s_cont = (*(volatile int*)&g_diff > it);
        __syncthreads();
        if (!s_cont) break;
    }

    // output: keep == D (== P at fixpoint)
    if (gtid < NBOX) {
        u64 kw = g_D[gtid >> 6];
        float4 v = ((kw >> (gtid & 63)) & 1ULL) ? g_seph[gtid]
                                                : make_float4(0.f, 0.f, 0.f, 0.f);
        out[gtid] = v;
    }
}

extern "C" void kernel_launch(void* const* d_in, const int* in_sizes, int n_in,
                              void* d_out, int out_size) {
    const float* in = (const float*)d_in[0];
    float4* out = (float4*)d_out;
    (void)in_sizes; (void)n_in; (void)out_size;

    k_sort<<<NBLK_S, 256>>>(in);
    k_mask<<<dim3(256, 256), 64>>>();
    k_fix <<<NBLK_F, 256>>>(out);
}

// round 16
// speedup vs baseline: 1.6126x; 1.3307x over previous
#include <cuda_runtime.h>

#define NBOX 16384
#define NW   256            // 64-bit words per mask row
#define NBKT 16384          // conf buckets for counting sort
#define NBLK 128            // persistent fixpoint CTAs (must be <= SM count)
#define CONF_THRESH 0.5f
#define PIOU_THRESH 0.5f

typedef unsigned long long u64;

// ---------------- device scratch (static; no allocation) ----------------
__device__ float4 g_seph[NBOX];                    // sorted [start,end,peak,height]
__device__ float  g_conf[NBOX];                    // dense confidence (unsorted)
__device__ int    g_hist[NBKT];
__device__ int    g_off[NBKT];
__device__ int    g_cnt[NBKT];
__device__ int    g_blist[NBOX];
__device__ int    g_M;
__device__ u64    g_mask[(size_t)NBOX * NW];       // 32MB suppression bitmask
__device__ u64    g_D[NW];                         // definitely-kept bitmap
__device__ u64    g_suppD[NW];                     // accumulated suppr(D)
__device__ int    g_ulist[2][NBOX];
__device__ int    g_dlist[2][NBOX];
__device__ int    g_un[2], g_dn[2];
__device__ int    g_arrive[NBLK];                  // distributed barrier slots
__device__ int    g_flag;                          // barrier release flag
__device__ int    g_diff;

__device__ __forceinline__ int bucket_of(float c) {
    int b = (int)(c * 16384.0f);                   // exact pow2 mul; monotone
    return b > 16383 ? 16383 : b;
}

// ---------------- 1) gather conf, zero accumulators ----------------
__global__ void k_prep(const float* __restrict__ in) {
    int i = blockIdx.x * blockDim.x + threadIdx.x;
    if (i < NBOX) {
        g_conf[i] = in[i * 5 + 0];
        g_hist[i] = 0;
        g_cnt[i]  = 0;
    }
    if (i == 0) g_M = 0;
}

// ---------------- 2a) bucket histogram ----------------
__global__ void k_hist() {
    int i = blockIdx.x * blockDim.x + threadIdx.x;
    if (i < NBOX) atomicAdd(&g_hist[bucket_of(g_conf[i])], 1);
}

// ---------------- 2b) suffix sums: off[b] = #elements with bucket > b ----------
__global__ void k_suffix() {                       // 1 block, 1024 threads
    __shared__ int part[1024];
    int t = threadIdx.x;
    int base = t * 16;
    int v[16]; int s = 0;
#pragma unroll
    for (int k = 0; k < 16; k++) { v[k] = g_hist[base + k]; s += v[k]; }
    part[t] = s;
    __syncthreads();
    for (int off = 1; off < 1024; off <<= 1) {     // inclusive suffix scan of partials
        int x = (t + off < 1024) ? part[t + off] : 0;
        __syncthreads();
        part[t] += x;
        __syncthreads();
    }
    int above = part[t] - s;                       // sum of buckets >= (t+1)*16
    int o[16];
    o[15] = above;
#pragma unroll
    for (int k = 14; k >= 0; k--) o[k] = o[k + 1] + v[k + 1];
#pragma unroll
    for (int k = 0; k < 16; k++) g_off[base + k] = o[k];
}

// ---------------- 2c) scatter indices into bucket segments ----------------
__global__ void k_bscatter() {
    int i = blockIdx.x * blockDim.x + threadIdx.x;
    if (i >= NBOX) return;
    int b = bucket_of(g_conf[i]);
    int pos = g_off[b] + atomicAdd(&g_cnt[b], 1);
    g_blist[pos] = i;
}

// ---------------- 3) exact rank within bucket + scatter boxes ----------------
__global__ void k_rankscatter(const float* __restrict__ in) {
    int i = blockIdx.x * blockDim.x + threadIdx.x;
    if (i >= NBOX) return;
    float ci = g_conf[i];
    int b    = bucket_of(ci);
    int base = g_off[b], len = g_hist[b];
    int cnt = 0;
    for (int p = base; p < base + len; p++) {
        int j = g_blist[p];
        float cj = g_conf[j];
        cnt += (cj > ci) || (cj == ci && j < i);   // stable: (conf desc, idx asc)
    }
    int r = base + cnt;
    const float* row = in + (size_t)i * 5;
    g_seph[r] = make_float4(row[1], row[2], row[3], row[4]);
    if (ci > CONF_THRESH) atomicAdd(&g_M, 1);
}

// ---------------- 4) pairwise peak-IoU bitmask, upper-triangular blocks only ----
__global__ void k_mask() {
    __shared__ float4 cols[64];
    if (blockIdx.x < blockIdx.y) return;           // triangular: halves the work
    int M = g_M;
    if ((int)(blockIdx.y * 64) >= M) return;
    int j0 = blockIdx.x * 64;
    if (j0 >= M) return;
    int r = blockIdx.y * 64 + threadIdx.x;
    cols[threadIdx.x] = g_seph[j0 + threadIdx.x];
    __syncthreads();
    if (r >= M) return;
    float4 a = g_seph[r];
    float area1 = __fmul_rn(__fsub_rn(a.y, a.x), a.w);
    u64 w = 0;
#pragma unroll 4
    for (int k = 0; k < 64; k++) {
        float4 b = cols[k];
        float is = fmaxf(a.x, b.x);
        float ie = fminf(a.y, b.y);
        float il = __fsub_rn(ie, is);
        bool sup = false;
        if (il > 0.0f) {                           // piou>0 requires overlap
            float inter_h    = fminf(a.w, b.w);
            float inter_area = __fmul_rn(il, inter_h);
            float area2      = __fmul_rn(__fsub_rn(b.y, b.x), b.w);
            float union_area = __fsub_rn(__fadd_rn(area1, area2), inter_area);
            float iou        = __fdiv_rn(inter_area, union_area);
            float pd         = fabsf(__fsub_rn(a.z, b.z));
            float us         = fminf(a.x, b.x);
            float ue         = fmaxf(a.y, b.y);
            float ud         = fabsf(__fsub_rn(ue, us));
            float val        = __fsub_rn(iou, __fdiv_rn(pd, ud));
            sup = (val > PIOU_THRESH);
        }
        w |= ((u64)sup) << k;
    }
    int lim = M - j0;
    if (lim < 64) w &= (1ULL << lim) - 1ULL;
    if (r >= j0 && r < j0 + 64) w &= ~(1ULL << (r - j0));
    g_mask[(size_t)r * NW + blockIdx.x] = w;
}

// ---------------- 5) persistent incremental fixpoint NMS ----------------
// Distributed-arrival grid barrier: each CTA leader stores to its OWN slot
// (no RMW serialization); CTA0's threads poll all slots in parallel, then
// release a flag. Values grow monotonically across graph replays; barrier
// count per launch is deterministic, so every slot ends each launch equal,
// and each CTA reads its own slot (single-writer) as the baseline.
__device__ __forceinline__ void gridsync(int& gen) {
    int next = gen + 1;
    __syncthreads();
    if (blockIdx.x == 0) {
        if (threadIdx.x == 0) {
            __threadfence();                       // publish CTA0's writes
            *(volatile int*)&g_arrive[0] = next;
        }
        if (threadIdx.x < NBLK) {
            while (*(volatile int*)&g_arrive[threadIdx.x] < next) { }
        }
        __syncthreads();                           // all slots observed
        if (threadIdx.x == 0) {
            __threadfence();                       // acquire + order release
            *(volatile int*)&g_flag = next;
        }
    } else {
        if (threadIdx.x == 0) {
            __threadfence();                       // publish our writes
            *(volatile int*)&g_arrive[blockIdx.x] = next;
            while (*(volatile int*)&g_flag < next) { }
            __threadfence();                       // acquire
        }
    }
    gen = next;
    __syncthreads();
}

__device__ __forceinline__ u64 trim_diag(u64 v, int j, int wtop) {
    if (j >= wtop) {                               // diagonal word: keep bits > bj
        int bj = j & 63;
        v = (bj == 63) ? 0ULL : (v & (~0ULL << (bj + 1)));
    }
    return v;
}

__device__ __forceinline__ u64 block_or(u64 v, u64* s_acc) {
#pragma unroll
    for (int o = 16; o > 0; o >>= 1)
        v |= __shfl_down_sync(0xffffffffu, v, o);
    if ((threadIdx.x & 31) == 0) s_acc[threadIdx.x >> 5] = v;
    __syncthreads();
    u64 r = 0ULL;
    if (threadIdx.x == 0) {
#pragma unroll
        for (int k = 0; k < 8; k++) r |= s_acc[k];
    }
    return r;                                      // valid on thread 0 only
}

__global__ void __launch_bounds__(256, 1) k_fix(float4* __restrict__ out) {
    __shared__ u64 s_acc[8];
    __shared__ int s_cont;
    __shared__ int s_gen;
    int tid  = threadIdx.x;
    int bid  = blockIdx.x;
    int gtid = bid * 256 + tid;                    // 0..32767
    if (tid == 0) s_gen = *(volatile int*)&g_arrive[bid];   // own slot: race-free
    __syncthreads();
    int gen = s_gen;
    int M  = g_M;
    int Mw = (M + 63) >> 6;

    // init
    if (gtid < NW) { g_suppD[gtid] = 0ULL; g_D[gtid] = 0ULL; }
    if (gtid == 0) {
        g_diff = 0;
        g_un[0] = g_un[1] = 0;
        g_dn[0] = g_dn[1] = 0;
    }
    gridsync(gen);

    for (int it = 0;; it++) {
        int e = it & 1;
        if (gtid == 0) g_un[e] = 0;                // next-epoch U counter
        // Phase A: Dnew = valid & ~(suppD | suppr(U_{it-1}))
        for (int w = bid; w < Mw; w += NBLK) {
            int hi   = (w + 1) << 6; if (hi > M) hi = M;
            int wtop = w << 6;
            u64 sup = 0ULL;
            if (it == 0) {                         // U_{-1} = all valid
#pragma unroll 4
                for (int j = tid; j < hi; j += 256)
                    sup |= trim_diag(g_mask[(size_t)j * NW + w], j, wtop);
            } else {
                int n = g_un[1 - e];
                const int* ul = g_ulist[1 - e];
#pragma unroll 4
                for (int p = tid; p < n; p += 256) {
                    int j = ul[p];
                    if (j < hi)
                        sup |= trim_diag(g_mask[(size_t)j * NW + w], j, wtop);
                }
            }
            sup = block_or(sup, s_acc);
            if (tid == 0) {
                sup |= g_suppD[w];
                int lim = M - wtop;
                u64 vm = (lim >= 64) ? ~0ULL : ((1ULL << lim) - 1ULL);
                u64 dn  = vm & ~sup;
                u64 add = dn & ~g_D[w];
                g_D[w] = dn;
                int na = __popcll(add);
                if (na) {
                    int base = atomicAdd(&g_dn[e], na);
                    while (add) {
                        int b = __ffsll((long long)add) - 1;
                        add &= add - 1ULL;
                        g_dlist[e][base++] = wtop + b;
                    }
                }
            }
            __syncthreads();
        }
        gridsync(gen);                             // S1: D + dlist complete
        if (gtid == 0) g_dn[1 - e] = 0;
        // Phase B: suppD |= suppr(Delta); P = valid & ~suppD; build U
        {
            int n = g_dn[e];
            const int* dl = g_dlist[e];
            for (int w = bid; w < Mw; w += NBLK) {
                int hi   = (w + 1) << 6; if (hi > M) hi = M;
                int wtop = w << 6;
                u64 sup = 0ULL;
#pragma unroll 4
                for (int p = tid; p < n; p += 256) {
                    int j = dl[p];
                    if (j < hi)
                        sup |= trim_diag(g_mask[(size_t)j * NW + w], j, wtop);
                }
                sup = block_or(sup, s_acc);
                if (tid == 0) {
                    u64 sd = g_suppD[w] | sup;
                    g_suppD[w] = sd;
                    int lim = M - wtop;
                    u64 vm = (lim >= 64) ? ~0ULL : ((1ULL << lim) - 1ULL);
                    u64 pn   = vm & ~sd;
                    u64 dcur = g_D[w];
                    if (pn != dcur) atomicMax(&g_diff, it + 1);
                    u64 undec = pn & ~dcur;
                    int nu = __popcll(undec);
                    if (nu) {
                        int base = atomicAdd(&g_un[e], nu);
                        while (undec) {
                            int b = __ffsll((long long)undec) - 1;
                            undec &= undec - 1ULL;
                            g_ulist[e][base++] = wtop + b;
                        }
                    }
                }
                __syncthreads();
            }
        }
        gridsync(gen);                             // S2: suppD/diff/ulist complete
        if (tid == 0) s_cont = (*(volatile int*)&g_diff > it);
        __syncthreads();
        if (!s_cont) break;
    }

    // output: keep == D (== P at fixpoint)
    if (gtid < NBOX) {
        u64 kw = g_D[gtid >> 6];
        float4 v = ((kw >> (gtid & 63)) & 1ULL) ? g_seph[gtid]
                                                : make_float4(0.f, 0.f, 0.f, 0.f);
        out[gtid] = v;
    }
}

extern "C" void kernel_launch(void* const* d_in, const int* in_sizes, int n_in,
                              void* d_out, int out_size) {
    const float* in = (const float*)d_in[0];
    float4* out = (float4*)d_out;
    (void)in_sizes; (void)n_in; (void)out_size;

    k_prep       <<<64, 256>>>(in);
    k_hist       <<<64, 256>>>();
    k_suffix     <<<1, 1024>>>();
    k_bscatter   <<<64, 256>>>();
    k_rankscatter<<<64, 256>>>(in);
    k_mask       <<<dim3(256, 256), 64>>>();
    k_fix        <<<NBLK, 256>>>(out);
}